// round 8
// baseline (speedup 1.0000x reference)
#include <cuda_runtime.h>
#include <cstdint>

typedef unsigned short ushort_t;

#define N_NODES   100000
#define N_EDGES   800000
#define HIDF      128
#define EMBF      64
#define OUTF      8
#define N_GRAPHS  64
#define ELLPAD    64
#define SENT      N_NODES   // sentinel index -> zero dummy row

// ---------------- scratch (device globals; no allocation) ----------------
__device__ int   g_batch[N_NODES];
__device__ int   g_deg[N_NODES];
__device__ int   g_ell[(size_t)N_NODES * ELLPAD];
__device__ float g_x  [(size_t)(N_NODES + 1) * HIDF];   // padded fp32 copy of x
__device__ float g_h1 [(size_t)(N_NODES + 1) * HIDF];   // +1 zero dummy row
__device__ float g_h2 [(size_t)N_NODES * HIDF];
// bf16 hi/lo planes
__device__ ushort_t g_xh [(size_t)N_NODES * HIDF];
__device__ ushort_t g_xl [(size_t)N_NODES * HIDF];
__device__ ushort_t g_h1h[(size_t)N_NODES * HIDF];
__device__ ushort_t g_h1l[(size_t)N_NODES * HIDF];
__device__ ushort_t g_agh[(size_t)N_NODES * HIDF];
__device__ ushort_t g_agl[(size_t)N_NODES * HIDF];
// weights pre-split to bf16 hi/lo, layout [128 out][256 k] row-major
__device__ ushort_t g_wh1[128 * 256];
__device__ ushort_t g_wl1[128 * 256];
__device__ ushort_t g_wh2[128 * 256];
__device__ ushort_t g_wl2[128 * 256];
__device__ float g_pool[N_GRAPHS * HIDF];
__device__ int   g_cnt[N_GRAPHS];

// ---------------- helpers ----------------
__device__ __forceinline__ uint32_t smem_u32(const void* p) {
    uint32_t a;
    asm("{ .reg .u64 t; cvta.to.shared.u64 t, %1; cvt.u32.u64 %0, t; }" : "=r"(a) : "l"(p));
    return a;
}
__device__ __forceinline__ void bf_split(float v, ushort_t& h, ushort_t& l) {
    asm("cvt.rn.bf16.f32 %0, %1;" : "=h"(h) : "f"(v));
    float hf = __uint_as_float(((unsigned)h) << 16);
    float r = v - hf;
    asm("cvt.rn.bf16.f32 %0, %1;" : "=h"(l) : "f"(r));
}
// int64-vs-int32 detection from 8 fixed odd 32-bit words of edge_index.
__device__ __forceinline__ int ei_is64(const unsigned* w) {
    unsigned o = w[1] | w[3] | w[5] | w[7] | w[9] | w[11] | w[13] | w[15];
    return o == 0u;
}
__device__ __forceinline__ void cp16(uint32_t dst, const void* src) {
    asm volatile("cp.async.cg.shared.global [%0], [%1], 16;" :: "r"(dst), "l"(src));
}
__device__ __forceinline__ void cp16z(uint32_t dst, const void* src, bool ok) {
    int sz = ok ? 16 : 0;
    asm volatile("cp.async.cg.shared.global [%0], [%1], 16, %2;"
                 :: "r"(dst), "l"(src), "r"(sz));
}
#define CP_COMMIT() asm volatile("cp.async.commit_group;" ::: "memory")
#define CP_WAIT(n)  asm volatile("cp.async.wait_group %0;" :: "n"(n) : "memory")

__device__ __forceinline__ void ldsm_x4(unsigned* r, uint32_t a) {
    asm volatile("ldmatrix.sync.aligned.m8n8.x4.shared.b16 {%0,%1,%2,%3}, [%4];"
                 : "=r"(r[0]), "=r"(r[1]), "=r"(r[2]), "=r"(r[3]) : "r"(a));
}
__device__ __forceinline__ void ldsm_x2(unsigned* r, uint32_t a) {
    asm volatile("ldmatrix.sync.aligned.m8n8.x2.shared.b16 {%0,%1}, [%2];"
                 : "=r"(r[0]), "=r"(r[1]) : "r"(a));
}
__device__ __forceinline__ void mma_bf16(float* c, const unsigned* a, const unsigned* b) {
    asm volatile(
        "mma.sync.aligned.m16n8k16.row.col.f32.bf16.bf16.f32 "
        "{%0,%1,%2,%3}, {%4,%5,%6,%7}, {%8,%9}, {%0,%1,%2,%3};"
        : "+f"(c[0]), "+f"(c[1]), "+f"(c[2]), "+f"(c[3])
        : "r"(a[0]), "r"(a[1]), "r"(a[2]), "r"(a[3]), "r"(b[0]), "r"(b[1]));
}

// ---------------- fused prep: x copy/split + weights + batch + ELL init ----------------
__global__ void k_prep_init(const float* __restrict__ x, const void* __restrict__ ei,
                            const void* __restrict__ batch,
                            const float* __restrict__ W1l, const float* __restrict__ W1r,
                            const float* __restrict__ W2l, const float* __restrict__ W2r) {
    int idx = blockIdx.x * blockDim.x + threadIdx.x;
    const int n4 = N_NODES * HIDF / 4;
    if (idx < n4) {  // copy x (padded fp32) + split to bf16 hi/lo planes
        float4 v = ((const float4*)x)[idx];
        ((float4*)g_x)[idx] = v;
        ushort_t h0, h1, h2, h3, l0, l1, l2, l3;
        bf_split(v.x, h0, l0); bf_split(v.y, h1, l1);
        bf_split(v.z, h2, l2); bf_split(v.w, h3, l3);
        ushort4 hv; hv.x = h0; hv.y = h1; hv.z = h2; hv.w = h3;
        ushort4 lv; lv.x = l0; lv.y = l1; lv.z = l2; lv.w = l3;
        ((ushort4*)g_xh)[idx] = hv;
        ((ushort4*)g_xl)[idx] = lv;
    }
    if (idx < 128 * 256) {  // weight concat + split
        int j = idx >> 8, k = idx & 255;
        float w1 = (k < 128) ? W1l[j * 128 + k] : W1r[j * 128 + (k - 128)];
        float w2 = (k < 128) ? W2l[j * 128 + k] : W2r[j * 128 + (k - 128)];
        ushort_t h, l;
        bf_split(w1, h, l); g_wh1[idx] = h; g_wl1[idx] = l;
        bf_split(w2, h, l); g_wh2[idx] = h; g_wl2[idx] = l;
    }
    if (idx < N_NODES) {  // batch convert + zero deg + sentinel-fill ELL row
        int is64 = ei_is64((const unsigned*)ei);
        if (is64) g_batch[idx] = (int)((const long long*)batch)[idx];
        else      g_batch[idx] = ((const int*)batch)[idx];
        g_deg[idx] = 0;
        int4 s4; s4.x = SENT; s4.y = SENT; s4.z = SENT; s4.w = SENT;
        int4* row = (int4*)(g_ell + (size_t)idx * ELLPAD);
#pragma unroll
        for (int q = 0; q < ELLPAD / 4; q++) row[q] = s4;
    }
    if (idx < HIDF / 4) {  // zero dummy rows (sentinel target)
        float4 z = make_float4(0.f, 0.f, 0.f, 0.f);
        ((float4*)(g_x  + (size_t)N_NODES * HIDF))[idx] = z;
        ((float4*)(g_h1 + (size_t)N_NODES * HIDF))[idx] = z;
    }
    if (idx < N_GRAPHS * HIDF) g_pool[idx] = 0.f;
    if (idx < N_GRAPHS)        g_cnt[idx]  = 0;
}

// ---------------- ELL build: convert edges inline + atomic cursor ----------------
__global__ void k_fill_ell(const void* __restrict__ ei) {
    int i = blockIdx.x * blockDim.x + threadIdx.x;
    if (i >= N_EDGES) return;
    int is64 = ei_is64((const unsigned*)ei);
    int s, d;
    if (is64) {
        const long long* p = (const long long*)ei;
        s = (int)p[i];
        d = (int)p[N_EDGES + i];
    } else {
        const int* p = (const int*)ei;
        s = p[i];
        d = p[N_EDGES + i];
    }
    int slot = atomicAdd(&g_deg[d], 1);
    if (slot < ELLPAD) g_ell[(size_t)d * ELLPAD + slot] = s;
}

// ---------------- mean aggregation (sentinel ELL): one warp per node, MLP=8 ----------------
// Pad slots hold SENT -> zero dummy row; every load unconditional.
__global__ void k_agg(const float* __restrict__ H,
                      ushort_t* __restrict__ Ph, ushort_t* __restrict__ Pl) {
    int node = (blockIdx.x * blockDim.x + threadIdx.x) >> 5;
    int lane = threadIdx.x & 31;
    if (node >= N_NODES) return;
    const int* ell = g_ell + (size_t)node * ELLPAD;
    int d = g_deg[node];
    int dcap = min(d, ELLPAD);
    int nb = (dcap + 7) & ~7;          // round up to 8; pads are sentinel
    float4 acc = make_float4(0.f, 0.f, 0.f, 0.f);
    for (int e = 0; e < nb; e += 8) {
        int id[8];
#pragma unroll
        for (int j = 0; j < 8; j++) id[j] = ell[e + j];
        float4 v[8];
#pragma unroll
        for (int j = 0; j < 8; j++)
            v[j] = ((const float4*)(H + (size_t)id[j] * HIDF))[lane];
#pragma unroll
        for (int j = 0; j < 8; j++) {
            acc.x += v[j].x; acc.y += v[j].y;
            acc.z += v[j].z; acc.w += v[j].w;
        }
    }
    float inv = 1.0f / (float)max(d, 1);
    acc.x *= inv; acc.y *= inv; acc.z *= inv; acc.w *= inv;
    ushort_t h0, h1, h2, h3, l0, l1, l2, l3;
    bf_split(acc.x, h0, l0); bf_split(acc.y, h1, l1);
    bf_split(acc.z, h2, l2); bf_split(acc.w, h3, l3);
    ushort4 hv; hv.x = h0; hv.y = h1; hv.z = h2; hv.w = h3;
    ushort4 lv; lv.x = l0; lv.y = l1; lv.z = l2; lv.w = l3;
    size_t o = (size_t)node * HIDF + lane * 4;
    *(ushort4*)(Ph + o) = hv;
    *(ushort4*)(Pl + o) = lv;
}

// ---------------- cp.async double-buffered bf16-split HMMA GEMM ----------------
#define SSTR 40
#define TS   (128 * SSTR)      // ushorts per tile
#define GSMEM (2 * 4 * TS * 2) // bytes: 2 stages x 4 tiles

__device__ __forceinline__ void stage_issue(
    int kb, int s, int row0, int r, int colseg, bool okA, uint32_t sb,
    const ushort_t* Aph, const ushort_t* Apl,
    const ushort_t* Hph, const ushort_t* Hpl,
    const ushort_t* Wh, const ushort_t* Wl)
{
    const ushort_t* Sh = (kb < 4) ? Aph : Hph;
    const ushort_t* Sl = (kb < 4) ? Apl : Hpl;
    int kc = (kb & 3) * 32;
    int k0 = kb * 32;
    uint32_t off  = (uint32_t)(r * SSTR + colseg) * 2;
    uint32_t base = sb + (uint32_t)s * 4 * TS * 2;
    const ushort_t* gah = Sh + (size_t)(row0 + r) * HIDF + kc + colseg;
    const ushort_t* gal = Sl + (size_t)(row0 + r) * HIDF + kc + colseg;
    cp16z(base + 0 * TS * 2 + off,      gah,     okA);
    cp16z(base + 0 * TS * 2 + off + 16, gah + 8, okA);
    cp16z(base + 1 * TS * 2 + off,      gal,     okA);
    cp16z(base + 1 * TS * 2 + off + 16, gal + 8, okA);
    const ushort_t* gbh = Wh + (size_t)r * 256 + k0 + colseg;
    const ushort_t* gbl = Wl + (size_t)r * 256 + k0 + colseg;
    cp16(base + 2 * TS * 2 + off,      gbh);
    cp16(base + 2 * TS * 2 + off + 16, gbh + 8);
    cp16(base + 3 * TS * 2 + off,      gbl);
    cp16(base + 3 * TS * 2 + off + 16, gbl + 8);
    CP_COMMIT();
}

__global__ void __launch_bounds__(256)
k_gemm_pipe(const ushort_t* __restrict__ Aph, const ushort_t* __restrict__ Apl,
            const ushort_t* __restrict__ Hph, const ushort_t* __restrict__ Hpl,
            const ushort_t* __restrict__ Wh,  const ushort_t* __restrict__ Wl,
            const float* __restrict__ bias, float* __restrict__ Hout,
            ushort_t* __restrict__ Hoh, ushort_t* __restrict__ Hol) {
    extern __shared__ ushort_t sdyn[];
    __shared__ float bsm[128];
    uint32_t sb = smem_u32(sdyn);
    int tid = threadIdx.x;
    int warp = tid >> 5, lane = tid & 31;
    int wm = warp & 1, wn = warp >> 1;        // 2 x 4 warp grid
    int gq = lane >> 2, tig = lane & 3;       // quad-pair layout
    int row0 = blockIdx.x * 128;
    if (tid < 128) bsm[tid] = bias[tid];

    int r = tid >> 1;
    int colseg = (tid & 1) * 16;
    bool okA = (row0 + r) < N_NODES;
    int arow = (lane & 7) + 8 * ((lane >> 3) & 1);
    int akof = 8 * (lane >> 4);
    int brow = lane & 7;
    int bkof = 8 * ((lane >> 3) & 1);

    float acc[4][4][4];
#pragma unroll
    for (int mi = 0; mi < 4; mi++)
#pragma unroll
        for (int ni = 0; ni < 4; ni++)
#pragma unroll
            for (int q = 0; q < 4; q++) acc[mi][ni][q] = 0.f;

    stage_issue(0, 0, row0, r, colseg, okA, sb, Aph, Apl, Hph, Hpl, Wh, Wl);

    for (int kb = 0; kb < 8; kb++) {
        int s = kb & 1;
        if (kb < 7) {
            stage_issue(kb + 1, s ^ 1, row0, r, colseg, okA, sb, Aph, Apl, Hph, Hpl, Wh, Wl);
            CP_WAIT(1);
        } else {
            CP_WAIT(0);
        }
        __syncthreads();
        uint32_t ah_s = sb + (uint32_t)(s * 4 + 0) * TS * 2;
        uint32_t al_s = sb + (uint32_t)(s * 4 + 1) * TS * 2;
        uint32_t bh_s = sb + (uint32_t)(s * 4 + 2) * TS * 2;
        uint32_t bl_s = sb + (uint32_t)(s * 4 + 3) * TS * 2;
#pragma unroll
        for (int ks = 0; ks < 2; ks++) {
            int koff = ks * 16;
            unsigned ahf[4][4], alf[4][4], bhf[4][2], blf[4][2];
#pragma unroll
            for (int mi = 0; mi < 4; mi++) {
                uint32_t off = (uint32_t)(((wm * 64 + mi * 16 + arow) * SSTR + koff + akof) * 2);
                ldsm_x4(ahf[mi], ah_s + off);
                ldsm_x4(alf[mi], al_s + off);
            }
#pragma unroll
            for (int ni = 0; ni < 4; ni++) {
                uint32_t off = (uint32_t)(((wn * 32 + ni * 8 + brow) * SSTR + koff + bkof) * 2);
                ldsm_x2(bhf[ni], bh_s + off);
                ldsm_x2(blf[ni], bl_s + off);
            }
#pragma unroll
            for (int mi = 0; mi < 4; mi++)
#pragma unroll
                for (int ni = 0; ni < 4; ni++) {
                    mma_bf16(acc[mi][ni], ahf[mi], bhf[ni]);
                    mma_bf16(acc[mi][ni], ahf[mi], blf[ni]);
                    mma_bf16(acc[mi][ni], alf[mi], bhf[ni]);
                }
        }
        __syncthreads();
    }
    // ---- epilogue + optional plane writes ----
    bool wrp = (Hoh != nullptr);
#pragma unroll
    for (int mi = 0; mi < 4; mi++) {
#pragma unroll
        for (int ni = 0; ni < 4; ni++) {
            int colc = wn * 32 + ni * 8 + tig * 2;
            int ra = row0 + wm * 64 + mi * 16 + gq;
            int rb = ra + 8;
            if (ra < N_NODES) {
                float2 o;
                o.x = fmaxf(acc[mi][ni][0] + bsm[colc], 0.f);
                o.y = fmaxf(acc[mi][ni][1] + bsm[colc + 1], 0.f);
                *(float2*)(Hout + (size_t)ra * HIDF + colc) = o;
                if (wrp) {
                    ushort_t hx, lx, hy, ly;
                    bf_split(o.x, hx, lx); bf_split(o.y, hy, ly);
                    ushort2 hv; hv.x = hx; hv.y = hy;
                    ushort2 lv; lv.x = lx; lv.y = ly;
                    *(ushort2*)(Hoh + (size_t)ra * HIDF + colc) = hv;
                    *(ushort2*)(Hol + (size_t)ra * HIDF + colc) = lv;
                }
            }
            if (rb < N_NODES) {
                float2 o;
                o.x = fmaxf(acc[mi][ni][2] + bsm[colc], 0.f);
                o.y = fmaxf(acc[mi][ni][3] + bsm[colc + 1], 0.f);
                *(float2*)(Hout + (size_t)rb * HIDF + colc) = o;
                if (wrp) {
                    ushort_t hx, lx, hy, ly;
                    bf_split(o.x, hx, lx); bf_split(o.y, hy, ly);
                    ushort2 hv; hv.x = hx; hv.y = hy;
                    ushort2 lv; lv.x = lx; lv.y = ly;
                    *(ushort2*)(Hoh + (size_t)rb * HIDF + colc) = hv;
                    *(ushort2*)(Hol + (size_t)rb * HIDF + colc) = lv;
                }
            }
        }
    }
}

// ---------------- sorted segment-mean pooling ----------------
__global__ void k_pool(const float* __restrict__ H) {
    int t = threadIdx.x;
    int base = blockIdx.x * 512;
    if (base >= N_NODES) return;
    int end = min(base + 512, N_NODES);
    int cur = g_batch[base];
    float acc = 0.f;
    int run = 0;
    for (int n = base; n < end; n++) {
        int g = g_batch[n];
        if (g != cur) {
            atomicAdd(&g_pool[cur * HIDF + t], acc);
            if (t == 0) atomicAdd(&g_cnt[cur], run);
            acc = 0.f; run = 0; cur = g;
        }
        acc += H[(size_t)n * HIDF + t];
        run++;
    }
    atomicAdd(&g_pool[cur * HIDF + t], acc);
    if (t == 0) atomicAdd(&g_cnt[cur], run);
}

// ---------------- head ----------------
__global__ void k_head(const float* __restrict__ embed, const float* __restrict__ Wlin,
                       const float* __restrict__ blin, float* __restrict__ out) {
    int t = threadIdx.x;
    if (t >= N_GRAPHS * OUTF) return;
    int g = t >> 3, o = t & 7;
    float c = (float)max(g_cnt[g], 1);
    float inv = 1.0f / c;
    const float* wr = Wlin + o * (HIDF + EMBF);
    float s = 0.f;
    for (int k = 0; k < HIDF; k++) s += g_pool[g * HIDF + k] * inv * wr[k];
    for (int k = 0; k < EMBF; k++) s += embed[g * EMBF + k] * wr[HIDF + k];
    out[g * OUTF + o] = s + blin[o];
}

// ---------------- launch ----------------
extern "C" void kernel_launch(void* const* d_in, const int* in_sizes, int n_in,
                              void* d_out, int out_size) {
    const float* x     = (const float*)d_in[0];
    const void*  ei    = d_in[1];
    const void*  batch = d_in[2];
    const float* embed = (const float*)d_in[3];
    const float* W1l   = (const float*)d_in[4];
    const float* b1l   = (const float*)d_in[5];
    const float* W1r   = (const float*)d_in[6];
    const float* W2l   = (const float*)d_in[7];
    const float* b2l   = (const float*)d_in[8];
    const float* W2r   = (const float*)d_in[9];
    const float* Wlin  = (const float*)d_in[10];
    const float* blin  = (const float*)d_in[11];
    float* out = (float*)d_out;

    float *x_p, *h1_p, *h2_p;
    ushort_t *xh_p, *xl_p, *h1h_p, *h1l_p, *agh_p, *agl_p;
    ushort_t *wh1_p, *wl1_p, *wh2_p, *wl2_p;
    cudaGetSymbolAddress((void**)&x_p,   g_x);
    cudaGetSymbolAddress((void**)&h1_p,  g_h1);
    cudaGetSymbolAddress((void**)&h2_p,  g_h2);
    cudaGetSymbolAddress((void**)&xh_p,  g_xh);
    cudaGetSymbolAddress((void**)&xl_p,  g_xl);
    cudaGetSymbolAddress((void**)&h1h_p, g_h1h);
    cudaGetSymbolAddress((void**)&h1l_p, g_h1l);
    cudaGetSymbolAddress((void**)&agh_p, g_agh);
    cudaGetSymbolAddress((void**)&agl_p, g_agl);
    cudaGetSymbolAddress((void**)&wh1_p, g_wh1);
    cudaGetSymbolAddress((void**)&wl1_p, g_wl1);
    cudaGetSymbolAddress((void**)&wh2_p, g_wh2);
    cudaGetSymbolAddress((void**)&wl2_p, g_wl2);

    cudaFuncSetAttribute(k_gemm_pipe, cudaFuncAttributeMaxDynamicSharedMemorySize, GSMEM);

    const int TB = 256;
    const int n4 = N_NODES * HIDF / 4;
    k_prep_init<<<(n4 + TB - 1) / TB, TB>>>(x, ei, batch, W1l, W1r, W2l, W2r);
    k_fill_ell<<<(N_EDGES + TB - 1) / TB, TB>>>(ei);

    const int NB = (N_NODES + 127) / 128;
    // layer 1 (aggregate reads padded fp32 copy of x)
    k_agg<<<(N_NODES + 7) / 8, 256>>>(x_p, agh_p, agl_p);
    k_gemm_pipe<<<NB, 256, GSMEM>>>(agh_p, agl_p, xh_p, xl_p, wh1_p, wl1_p,
                                    b1l, h1_p, h1h_p, h1l_p);
    // layer 2
    k_agg<<<(N_NODES + 7) / 8, 256>>>(h1_p, agh_p, agl_p);
    k_gemm_pipe<<<NB, 256, GSMEM>>>(agh_p, agl_p, h1h_p, h1l_p, wh2_p, wl2_p,
                                    b2l, h2_p, (ushort_t*)nullptr, (ushort_t*)nullptr);
    // pooling + head
    k_pool<<<(N_NODES + 511) / 512, 128>>>(h2_p);
    k_head<<<1, 512>>>(embed, Wlin, blin, out);
}

// round 9
// speedup vs baseline: 1.0215x; 1.0215x over previous
#include <cuda_runtime.h>
#include <cstdint>

typedef unsigned short ushort_t;

#define N_NODES   100000
#define N_EDGES   800000
#define HIDF      128
#define EMBF      64
#define OUTF      8
#define N_GRAPHS  64
#define ELLPAD    64

// ---------------- scratch (device globals; no allocation) ----------------
__device__ int   g_batch[N_NODES];
__device__ int   g_deg[N_NODES];
__device__ int   g_ell[(size_t)N_NODES * ELLPAD];
__device__ float g_h1 [(size_t)N_NODES * HIDF];
__device__ float g_h2 [(size_t)N_NODES * HIDF];
// bf16 hi/lo planes
__device__ ushort_t g_xh [(size_t)N_NODES * HIDF];
__device__ ushort_t g_xl [(size_t)N_NODES * HIDF];
__device__ ushort_t g_h1h[(size_t)N_NODES * HIDF];
__device__ ushort_t g_h1l[(size_t)N_NODES * HIDF];
__device__ ushort_t g_agh[(size_t)N_NODES * HIDF];
__device__ ushort_t g_agl[(size_t)N_NODES * HIDF];
// weights pre-split to bf16 hi/lo, layout [128 out][256 k] row-major
__device__ ushort_t g_wh1[128 * 256];
__device__ ushort_t g_wl1[128 * 256];
__device__ ushort_t g_wh2[128 * 256];
__device__ ushort_t g_wl2[128 * 256];
__device__ float g_pool[N_GRAPHS * HIDF];
__device__ int   g_cnt[N_GRAPHS];

// ---------------- helpers ----------------
__device__ __forceinline__ uint32_t smem_u32(const void* p) {
    uint32_t a;
    asm("{ .reg .u64 t; cvta.to.shared.u64 t, %1; cvt.u32.u64 %0, t; }" : "=r"(a) : "l"(p));
    return a;
}
__device__ __forceinline__ void bf_split(float v, ushort_t& h, ushort_t& l) {
    asm("cvt.rn.bf16.f32 %0, %1;" : "=h"(h) : "f"(v));
    float hf = __uint_as_float(((unsigned)h) << 16);
    float r = v - hf;
    asm("cvt.rn.bf16.f32 %0, %1;" : "=h"(l) : "f"(r));
}
// int64-vs-int32 detection from 8 fixed odd 32-bit words of edge_index.
__device__ __forceinline__ int ei_is64(const unsigned* w) {
    unsigned o = w[1] | w[3] | w[5] | w[7] | w[9] | w[11] | w[13] | w[15];
    return o == 0u;
}
__device__ __forceinline__ void cp16(uint32_t dst, const void* src) {
    asm volatile("cp.async.cg.shared.global [%0], [%1], 16;" :: "r"(dst), "l"(src));
}
__device__ __forceinline__ void cp16z(uint32_t dst, const void* src, bool ok) {
    int sz = ok ? 16 : 0;
    asm volatile("cp.async.cg.shared.global [%0], [%1], 16, %2;"
                 :: "r"(dst), "l"(src), "r"(sz));
}
#define CP_COMMIT() asm volatile("cp.async.commit_group;" ::: "memory")
#define CP_WAIT(n)  asm volatile("cp.async.wait_group %0;" :: "n"(n) : "memory")

__device__ __forceinline__ void ldsm_x4(unsigned* r, uint32_t a) {
    asm volatile("ldmatrix.sync.aligned.m8n8.x4.shared.b16 {%0,%1,%2,%3}, [%4];"
                 : "=r"(r[0]), "=r"(r[1]), "=r"(r[2]), "=r"(r[3]) : "r"(a));
}
__device__ __forceinline__ void ldsm_x2(unsigned* r, uint32_t a) {
    asm volatile("ldmatrix.sync.aligned.m8n8.x2.shared.b16 {%0,%1}, [%2];"
                 : "=r"(r[0]), "=r"(r[1]) : "r"(a));
}
__device__ __forceinline__ void mma_bf16(float* c, const unsigned* a, const unsigned* b) {
    asm volatile(
        "mma.sync.aligned.m16n8k16.row.col.f32.bf16.bf16.f32 "
        "{%0,%1,%2,%3}, {%4,%5,%6,%7}, {%8,%9}, {%0,%1,%2,%3};"
        : "+f"(c[0]), "+f"(c[1]), "+f"(c[2]), "+f"(c[3])
        : "r"(a[0]), "r"(a[1]), "r"(a[2]), "r"(a[3]), "r"(b[0]), "r"(b[1]));
}

// ---------------- fused prep: x split + weight split + batch + zeroing ----------------
__global__ void k_prep_init(const float* __restrict__ x, const void* __restrict__ ei,
                            const void* __restrict__ batch,
                            const float* __restrict__ W1l, const float* __restrict__ W1r,
                            const float* __restrict__ W2l, const float* __restrict__ W2r) {
    int idx = blockIdx.x * blockDim.x + threadIdx.x;
    const int n4 = N_NODES * HIDF / 4;
    if (idx < n4) {  // split x -> bf16 hi/lo planes
        float4 v = ((const float4*)x)[idx];
        ushort_t h0, h1, h2, h3, l0, l1, l2, l3;
        bf_split(v.x, h0, l0); bf_split(v.y, h1, l1);
        bf_split(v.z, h2, l2); bf_split(v.w, h3, l3);
        ushort4 hv; hv.x = h0; hv.y = h1; hv.z = h2; hv.w = h3;
        ushort4 lv; lv.x = l0; lv.y = l1; lv.z = l2; lv.w = l3;
        ((ushort4*)g_xh)[idx] = hv;
        ((ushort4*)g_xl)[idx] = lv;
    }
    if (idx < 128 * 256) {  // weight concat + split
        int j = idx >> 8, k = idx & 255;
        float w1 = (k < 128) ? W1l[j * 128 + k] : W1r[j * 128 + (k - 128)];
        float w2 = (k < 128) ? W2l[j * 128 + k] : W2r[j * 128 + (k - 128)];
        ushort_t h, l;
        bf_split(w1, h, l); g_wh1[idx] = h; g_wl1[idx] = l;
        bf_split(w2, h, l); g_wh2[idx] = h; g_wl2[idx] = l;
    }
    if (idx < N_NODES) {  // batch convert + zero deg
        int is64 = ei_is64((const unsigned*)ei);
        if (is64) g_batch[idx] = (int)((const long long*)batch)[idx];
        else      g_batch[idx] = ((const int*)batch)[idx];
        g_deg[idx] = 0;
    }
    if (idx < N_GRAPHS * HIDF) g_pool[idx] = 0.f;
    if (idx < N_GRAPHS)        g_cnt[idx]  = 0;
}

// ---------------- ELL build: convert edges inline + atomic cursor ----------------
__global__ void k_fill_ell(const void* __restrict__ ei) {
    int i = blockIdx.x * blockDim.x + threadIdx.x;
    if (i >= N_EDGES) return;
    int is64 = ei_is64((const unsigned*)ei);
    int s, d;
    if (is64) {
        const long long* p = (const long long*)ei;
        s = (int)p[i];
        d = (int)p[N_EDGES + i];
    } else {
        const int* p = (const int*)ei;
        s = p[i];
        d = p[N_EDGES + i];
    }
    int slot = atomicAdd(&g_deg[d], 1);
    if (slot < ELLPAD) g_ell[(size_t)d * ELLPAD + slot] = s;
}

// ---------------- no-op spacer so the profiler's capture slot lands on k_agg ----
__global__ void k_dummy() {}

// ---------------- mean aggregation (ELL): one warp per node (R6 form) ----------------
__global__ void k_agg(const float* __restrict__ H,
                      ushort_t* __restrict__ Ph, ushort_t* __restrict__ Pl) {
    int node = (blockIdx.x * blockDim.x + threadIdx.x) >> 5;
    int lane = threadIdx.x & 31;
    if (node >= N_NODES) return;
    const int* ell = g_ell + (size_t)node * ELLPAD;
    int d = g_deg[node];
    int dcap = min(d, ELLPAD);
    float4 acc = make_float4(0.f, 0.f, 0.f, 0.f);
    int e = 0;
    for (; e + 4 <= dcap; e += 4) {
        int s0 = ell[e], s1 = ell[e + 1], s2 = ell[e + 2], s3 = ell[e + 3];
        float4 v0 = ((const float4*)(H + (size_t)s0 * HIDF))[lane];
        float4 v1 = ((const float4*)(H + (size_t)s1 * HIDF))[lane];
        float4 v2 = ((const float4*)(H + (size_t)s2 * HIDF))[lane];
        float4 v3 = ((const float4*)(H + (size_t)s3 * HIDF))[lane];
        acc.x += (v0.x + v1.x) + (v2.x + v3.x);
        acc.y += (v0.y + v1.y) + (v2.y + v3.y);
        acc.z += (v0.z + v1.z) + (v2.z + v3.z);
        acc.w += (v0.w + v1.w) + (v2.w + v3.w);
    }
    for (; e < dcap; e++) {
        int s0 = ell[e];
        float4 v0 = ((const float4*)(H + (size_t)s0 * HIDF))[lane];
        acc.x += v0.x; acc.y += v0.y; acc.z += v0.z; acc.w += v0.w;
    }
    float inv = 1.0f / (float)max(d, 1);
    acc.x *= inv; acc.y *= inv; acc.z *= inv; acc.w *= inv;
    ushort_t h0, h1, h2, h3, l0, l1, l2, l3;
    bf_split(acc.x, h0, l0); bf_split(acc.y, h1, l1);
    bf_split(acc.z, h2, l2); bf_split(acc.w, h3, l3);
    ushort4 hv; hv.x = h0; hv.y = h1; hv.z = h2; hv.w = h3;
    ushort4 lv; lv.x = l0; lv.y = l1; lv.z = l2; lv.w = l3;
    size_t o = (size_t)node * HIDF + lane * 4;
    *(ushort4*)(Ph + o) = hv;
    *(ushort4*)(Pl + o) = lv;
}

// ---------------- cp.async double-buffered bf16-split HMMA GEMM ----------------
// Swizzled 64B-row tiles (no padding): physical 16B-chunk = c ^ ((row>>1)&3).
// Conflict-free per 8-lane ldmatrix phase; 16B aligned everywhere.
// smem: 2 stages x 4 tiles x 8KB = 64KB -> 3 CTAs/SM.
#define TILEB 8192
#define GSMEM (2 * 4 * TILEB)

__device__ __forceinline__ uint32_t swz(int r, int c) {
    return (uint32_t)((r << 6) + ((c ^ ((r >> 1) & 3)) << 4));
}

__device__ __forceinline__ void stage_issue(
    int kb, int s, int row0, int r, int colseg, bool okA, uint32_t sb,
    const ushort_t* Aph, const ushort_t* Apl,
    const ushort_t* Hph, const ushort_t* Hpl,
    const ushort_t* Wh, const ushort_t* Wl)
{
    const ushort_t* Sh = (kb < 4) ? Aph : Hph;
    const ushort_t* Sl = (kb < 4) ? Apl : Hpl;
    int kc = (kb & 3) * 32;
    int k0 = kb * 32;
    int c0 = colseg >> 3;              // 16B-chunk index: 0 or 2
    uint32_t base = sb + (uint32_t)s * 4 * TILEB;
    uint32_t d0 = swz(r, c0), d1 = swz(r, c0 + 1);
    const ushort_t* gah = Sh + (size_t)(row0 + r) * HIDF + kc + colseg;
    const ushort_t* gal = Sl + (size_t)(row0 + r) * HIDF + kc + colseg;
    cp16z(base + 0 * TILEB + d0, gah,     okA);
    cp16z(base + 0 * TILEB + d1, gah + 8, okA);
    cp16z(base + 1 * TILEB + d0, gal,     okA);
    cp16z(base + 1 * TILEB + d1, gal + 8, okA);
    const ushort_t* gbh = Wh + (size_t)r * 256 + k0 + colseg;
    const ushort_t* gbl = Wl + (size_t)r * 256 + k0 + colseg;
    cp16(base + 2 * TILEB + d0, gbh);
    cp16(base + 2 * TILEB + d1, gbh + 8);
    cp16(base + 3 * TILEB + d0, gbl);
    cp16(base + 3 * TILEB + d1, gbl + 8);
    CP_COMMIT();
}

__global__ void __launch_bounds__(256)
k_gemm_pipe(const ushort_t* __restrict__ Aph, const ushort_t* __restrict__ Apl,
            const ushort_t* __restrict__ Hph, const ushort_t* __restrict__ Hpl,
            const ushort_t* __restrict__ Wh,  const ushort_t* __restrict__ Wl,
            const float* __restrict__ bias, float* __restrict__ Hout,
            ushort_t* __restrict__ Hoh, ushort_t* __restrict__ Hol) {
    extern __shared__ ushort_t sdyn[];
    __shared__ float bsm[128];
    uint32_t sb = smem_u32(sdyn);
    int tid = threadIdx.x;
    int warp = tid >> 5, lane = tid & 31;
    int wm = warp & 1, wn = warp >> 1;        // 2 x 4 warp grid
    int gq = lane >> 2, tig = lane & 3;       // quad-pair layout
    int row0 = blockIdx.x * 128;
    if (tid < 128) bsm[tid] = bias[tid];

    int r = tid >> 1;
    int colseg = (tid & 1) * 16;
    bool okA = (row0 + r) < N_NODES;
    int arow = (lane & 7) + 8 * ((lane >> 3) & 1);   // A row within 16
    int achk = lane >> 4;                            // A chunk sub-index 0/1
    int brow = lane & 7;                             // B row (n)
    int bchk = (lane >> 3) & 1;                      // B chunk sub-index 0/1

    float acc[4][4][4];
#pragma unroll
    for (int mi = 0; mi < 4; mi++)
#pragma unroll
        for (int ni = 0; ni < 4; ni++)
#pragma unroll
            for (int q = 0; q < 4; q++) acc[mi][ni][q] = 0.f;

    stage_issue(0, 0, row0, r, colseg, okA, sb, Aph, Apl, Hph, Hpl, Wh, Wl);

    for (int kb = 0; kb < 8; kb++) {
        int s = kb & 1;
        if (kb < 7) {
            stage_issue(kb + 1, s ^ 1, row0, r, colseg, okA, sb, Aph, Apl, Hph, Hpl, Wh, Wl);
            CP_WAIT(1);
        } else {
            CP_WAIT(0);
        }
        __syncthreads();
        uint32_t ah_s = sb + (uint32_t)(s * 4 + 0) * TILEB;
        uint32_t al_s = sb + (uint32_t)(s * 4 + 1) * TILEB;
        uint32_t bh_s = sb + (uint32_t)(s * 4 + 2) * TILEB;
        uint32_t bl_s = sb + (uint32_t)(s * 4 + 3) * TILEB;
#pragma unroll
        for (int ks = 0; ks < 2; ks++) {
            int ca = ks * 2 + achk;   // logical 16B chunk for A
            int cb = ks * 2 + bchk;   // logical 16B chunk for B
            unsigned ahf[4][4], alf[4][4], bhf[4][2], blf[4][2];
#pragma unroll
            for (int mi = 0; mi < 4; mi++) {
                int m = wm * 64 + mi * 16 + arow;
                uint32_t off = swz(m, ca);
                ldsm_x4(ahf[mi], ah_s + off);
                ldsm_x4(alf[mi], al_s + off);
            }
#pragma unroll
            for (int ni = 0; ni < 4; ni++) {
                int n = wn * 32 + ni * 8 + brow;
                uint32_t off = swz(n, cb);
                ldsm_x2(bhf[ni], bh_s + off);
                ldsm_x2(blf[ni], bl_s + off);
            }
#pragma unroll
            for (int mi = 0; mi < 4; mi++)
#pragma unroll
                for (int ni = 0; ni < 4; ni++) {
                    mma_bf16(acc[mi][ni], ahf[mi], bhf[ni]);
                    mma_bf16(acc[mi][ni], ahf[mi], blf[ni]);
                    mma_bf16(acc[mi][ni], alf[mi], bhf[ni]);
                }
        }
        __syncthreads();
    }
    // ---- epilogue + optional plane writes ----
    bool wrp = (Hoh != nullptr);
#pragma unroll
    for (int mi = 0; mi < 4; mi++) {
#pragma unroll
        for (int ni = 0; ni < 4; ni++) {
            int colc = wn * 32 + ni * 8 + tig * 2;
            int ra = row0 + wm * 64 + mi * 16 + gq;
            int rb = ra + 8;
            if (ra < N_NODES) {
                float2 o;
                o.x = fmaxf(acc[mi][ni][0] + bsm[colc], 0.f);
                o.y = fmaxf(acc[mi][ni][1] + bsm[colc + 1], 0.f);
                *(float2*)(Hout + (size_t)ra * HIDF + colc) = o;
                if (wrp) {
                    ushort_t hx, lx, hy, ly;
                    bf_split(o.x, hx, lx); bf_split(o.y, hy, ly);
                    ushort2 hv; hv.x = hx; hv.y = hy;
                    ushort2 lv; lv.x = lx; lv.y = ly;
                    *(ushort2*)(Hoh + (size_t)ra * HIDF + colc) = hv;
                    *(ushort2*)(Hol + (size_t)ra * HIDF + colc) = lv;
                }
            }
            if (rb < N_NODES) {
                float2 o;
                o.x = fmaxf(acc[mi][ni][2] + bsm[colc], 0.f);
                o.y = fmaxf(acc[mi][ni][3] + bsm[colc + 1], 0.f);
                *(float2*)(Hout + (size_t)rb * HIDF + colc) = o;
                if (wrp) {
                    ushort_t hx, lx, hy, ly;
                    bf_split(o.x, hx, lx); bf_split(o.y, hy, ly);
                    ushort2 hv; hv.x = hx; hv.y = hy;
                    ushort2 lv; lv.x = lx; lv.y = ly;
                    *(ushort2*)(Hoh + (size_t)rb * HIDF + colc) = hv;
                    *(ushort2*)(Hol + (size_t)rb * HIDF + colc) = lv;
                }
            }
        }
    }
}

// ---------------- sorted segment-mean pooling ----------------
__global__ void k_pool(const float* __restrict__ H) {
    int t = threadIdx.x;
    int base = blockIdx.x * 512;
    if (base >= N_NODES) return;
    int end = min(base + 512, N_NODES);
    int cur = g_batch[base];
    float acc = 0.f;
    int run = 0;
    for (int n = base; n < end; n++) {
        int g = g_batch[n];
        if (g != cur) {
            atomicAdd(&g_pool[cur * HIDF + t], acc);
            if (t == 0) atomicAdd(&g_cnt[cur], run);
            acc = 0.f; run = 0; cur = g;
        }
        acc += H[(size_t)n * HIDF + t];
        run++;
    }
    atomicAdd(&g_pool[cur * HIDF + t], acc);
    if (t == 0) atomicAdd(&g_cnt[cur], run);
}

// ---------------- head ----------------
__global__ void k_head(const float* __restrict__ embed, const float* __restrict__ Wlin,
                       const float* __restrict__ blin, float* __restrict__ out) {
    int t = threadIdx.x;
    if (t >= N_GRAPHS * OUTF) return;
    int g = t >> 3, o = t & 7;
    float c = (float)max(g_cnt[g], 1);
    float inv = 1.0f / c;
    const float* wr = Wlin + o * (HIDF + EMBF);
    float s = 0.f;
    for (int k = 0; k < HIDF; k++) s += g_pool[g * HIDF + k] * inv * wr[k];
    for (int k = 0; k < EMBF; k++) s += embed[g * EMBF + k] * wr[HIDF + k];
    out[g * OUTF + o] = s + blin[o];
}

// ---------------- launch ----------------
extern "C" void kernel_launch(void* const* d_in, const int* in_sizes, int n_in,
                              void* d_out, int out_size) {
    const float* x     = (const float*)d_in[0];
    const void*  ei    = d_in[1];
    const void*  batch = d_in[2];
    const float* embed = (const float*)d_in[3];
    const float* W1l   = (const float*)d_in[4];
    const float* b1l   = (const float*)d_in[5];
    const float* W1r   = (const float*)d_in[6];
    const float* W2l   = (const float*)d_in[7];
    const float* b2l   = (const float*)d_in[8];
    const float* W2r   = (const float*)d_in[9];
    const float* Wlin  = (const float*)d_in[10];
    const float* blin  = (const float*)d_in[11];
    float* out = (float*)d_out;

    float *h1_p, *h2_p;
    ushort_t *xh_p, *xl_p, *h1h_p, *h1l_p, *agh_p, *agl_p;
    ushort_t *wh1_p, *wl1_p, *wh2_p, *wl2_p;
    cudaGetSymbolAddress((void**)&h1_p,  g_h1);
    cudaGetSymbolAddress((void**)&h2_p,  g_h2);
    cudaGetSymbolAddress((void**)&xh_p,  g_xh);
    cudaGetSymbolAddress((void**)&xl_p,  g_xl);
    cudaGetSymbolAddress((void**)&h1h_p, g_h1h);
    cudaGetSymbolAddress((void**)&h1l_p, g_h1l);
    cudaGetSymbolAddress((void**)&agh_p, g_agh);
    cudaGetSymbolAddress((void**)&agl_p, g_agl);
    cudaGetSymbolAddress((void**)&wh1_p, g_wh1);
    cudaGetSymbolAddress((void**)&wl1_p, g_wl1);
    cudaGetSymbolAddress((void**)&wh2_p, g_wh2);
    cudaGetSymbolAddress((void**)&wl2_p, g_wl2);

    cudaFuncSetAttribute(k_gemm_pipe, cudaFuncAttributeMaxDynamicSharedMemorySize, GSMEM);

    const int TB = 256;
    const int n4 = N_NODES * HIDF / 4;
    k_prep_init<<<(n4 + TB - 1) / TB, TB>>>(x, ei, batch, W1l, W1r, W2l, W2r);   // 1
    k_fill_ell<<<(N_EDGES + TB - 1) / TB, TB>>>(ei);                              // 2
    k_dummy<<<1, 32>>>();                                                          // 3 (spacer)

    const int NB = (N_NODES + 127) / 128;
    // layer 1
    k_agg<<<(N_NODES + 7) / 8, 256>>>(x, agh_p, agl_p);                           // 4 <- profiled
    k_gemm_pipe<<<NB, 256, GSMEM>>>(agh_p, agl_p, xh_p, xl_p, wh1_p, wl1_p,
                                    b1l, h1_p, h1h_p, h1l_p);                     // 5
    // layer 2
    k_agg<<<(N_NODES + 7) / 8, 256>>>(h1_p, agh_p, agl_p);                        // 6
    k_gemm_pipe<<<NB, 256, GSMEM>>>(agh_p, agl_p, h1h_p, h1l_p, wh2_p, wl2_p,
                                    b2l, h2_p, (ushort_t*)nullptr, (ushort_t*)nullptr);  // 7
    // pooling + head
    k_pool<<<(N_NODES + 511) / 512, 128>>>(h2_p);                                  // 8
    k_head<<<1, 512>>>(embed, Wlin, blin, out);                                    // 9
}

// round 10
// speedup vs baseline: 1.6211x; 1.5869x over previous
#include <cuda_runtime.h>
#include <cstdint>

typedef unsigned short ushort_t;

#define N_NODES   100000
#define N_EDGES   800000
#define HIDF      128
#define EMBF      64
#define OUTF      8
#define N_GRAPHS  64
#define ELLPAD    64

// ---------------- scratch (device globals; no allocation) ----------------
__device__ int   g_batch[N_NODES];
__device__ int   g_deg[N_NODES];
__device__ int   g_ell[(size_t)N_NODES * ELLPAD];
__device__ float g_h1 [(size_t)N_NODES * HIDF];
__device__ float g_h2 [(size_t)N_NODES * HIDF];
// bf16 hi/lo planes
__device__ ushort_t g_xh [(size_t)N_NODES * HIDF];
__device__ ushort_t g_xl [(size_t)N_NODES * HIDF];
__device__ ushort_t g_h1h[(size_t)N_NODES * HIDF];
__device__ ushort_t g_h1l[(size_t)N_NODES * HIDF];
__device__ ushort_t g_agh[(size_t)N_NODES * HIDF];
__device__ ushort_t g_agl[(size_t)N_NODES * HIDF];
// weights pre-split to bf16 hi/lo, layout [128 out][256 k] row-major
__device__ ushort_t g_wh1[128 * 256];
__device__ ushort_t g_wl1[128 * 256];
__device__ ushort_t g_wh2[128 * 256];
__device__ ushort_t g_wl2[128 * 256];
__device__ float g_pool[N_GRAPHS * HIDF];
__device__ int   g_cnt[N_GRAPHS];

// ---------------- helpers ----------------
__device__ __forceinline__ uint32_t smem_u32(const void* p) {
    uint32_t a;
    asm("{ .reg .u64 t; cvta.to.shared.u64 t, %1; cvt.u32.u64 %0, t; }" : "=r"(a) : "l"(p));
    return a;
}
__device__ __forceinline__ void bf_split(float v, ushort_t& h, ushort_t& l) {
    asm("cvt.rn.bf16.f32 %0, %1;" : "=h"(h) : "f"(v));
    float hf = __uint_as_float(((unsigned)h) << 16);
    float r = v - hf;
    asm("cvt.rn.bf16.f32 %0, %1;" : "=h"(l) : "f"(r));
}
// int64-vs-int32 detection from 8 fixed odd 32-bit words of edge_index.
__device__ __forceinline__ int ei_is64(const unsigned* w) {
    unsigned o = w[1] | w[3] | w[5] | w[7] | w[9] | w[11] | w[13] | w[15];
    return o == 0u;
}
__device__ __forceinline__ void cp16(uint32_t dst, const void* src) {
    asm volatile("cp.async.cg.shared.global [%0], [%1], 16;" :: "r"(dst), "l"(src));
}
__device__ __forceinline__ void cp16z(uint32_t dst, const void* src, bool ok) {
    int sz = ok ? 16 : 0;
    asm volatile("cp.async.cg.shared.global [%0], [%1], 16, %2;"
                 :: "r"(dst), "l"(src), "r"(sz));
}
#define CP_COMMIT() asm volatile("cp.async.commit_group;" ::: "memory")
#define CP_WAIT(n)  asm volatile("cp.async.wait_group %0;" :: "n"(n) : "memory")

__device__ __forceinline__ void ldsm_x4(unsigned* r, uint32_t a) {
    asm volatile("ldmatrix.sync.aligned.m8n8.x4.shared.b16 {%0,%1,%2,%3}, [%4];"
                 : "=r"(r[0]), "=r"(r[1]), "=r"(r[2]), "=r"(r[3]) : "r"(a));
}
__device__ __forceinline__ void ldsm_x2(unsigned* r, uint32_t a) {
    asm volatile("ldmatrix.sync.aligned.m8n8.x2.shared.b16 {%0,%1}, [%2];"
                 : "=r"(r[0]), "=r"(r[1]) : "r"(a));
}
__device__ __forceinline__ void mma_bf16(float* c, const unsigned* a, const unsigned* b) {
    asm volatile(
        "mma.sync.aligned.m16n8k16.row.col.f32.bf16.bf16.f32 "
        "{%0,%1,%2,%3}, {%4,%5,%6,%7}, {%8,%9}, {%0,%1,%2,%3};"
        : "+f"(c[0]), "+f"(c[1]), "+f"(c[2]), "+f"(c[3])
        : "r"(a[0]), "r"(a[1]), "r"(a[2]), "r"(a[3]), "r"(b[0]), "r"(b[1]));
}

// ---------------- fused prep: x split + weight split + batch + zeroing ----------------
__global__ void k_prep_init(const float* __restrict__ x, const void* __restrict__ ei,
                            const void* __restrict__ batch,
                            const float* __restrict__ W1l, const float* __restrict__ W1r,
                            const float* __restrict__ W2l, const float* __restrict__ W2r) {
    int idx = blockIdx.x * blockDim.x + threadIdx.x;
    const int n4 = N_NODES * HIDF / 4;
    if (idx < n4) {  // split x -> bf16 hi/lo planes
        float4 v = ((const float4*)x)[idx];
        ushort_t h0, h1, h2, h3, l0, l1, l2, l3;
        bf_split(v.x, h0, l0); bf_split(v.y, h1, l1);
        bf_split(v.z, h2, l2); bf_split(v.w, h3, l3);
        ushort4 hv; hv.x = h0; hv.y = h1; hv.z = h2; hv.w = h3;
        ushort4 lv; lv.x = l0; lv.y = l1; lv.z = l2; lv.w = l3;
        ((ushort4*)g_xh)[idx] = hv;
        ((ushort4*)g_xl)[idx] = lv;
    }
    if (idx < 128 * 256) {  // weight concat + split
        int j = idx >> 8, k = idx & 255;
        float w1 = (k < 128) ? W1l[j * 128 + k] : W1r[j * 128 + (k - 128)];
        float w2 = (k < 128) ? W2l[j * 128 + k] : W2r[j * 128 + (k - 128)];
        ushort_t h, l;
        bf_split(w1, h, l); g_wh1[idx] = h; g_wl1[idx] = l;
        bf_split(w2, h, l); g_wh2[idx] = h; g_wl2[idx] = l;
    }
    if (idx < N_NODES) {  // batch convert + zero deg
        int is64 = ei_is64((const unsigned*)ei);
        if (is64) g_batch[idx] = (int)((const long long*)batch)[idx];
        else      g_batch[idx] = ((const int*)batch)[idx];
        g_deg[idx] = 0;
    }
    if (idx < N_GRAPHS * HIDF) g_pool[idx] = 0.f;
    if (idx < N_GRAPHS)        g_cnt[idx]  = 0;
}

// ---------------- ELL build: convert edges inline + atomic cursor ----------------
__global__ void k_fill_ell(const void* __restrict__ ei) {
    int i = blockIdx.x * blockDim.x + threadIdx.x;
    if (i >= N_EDGES) return;
    int is64 = ei_is64((const unsigned*)ei);
    int s, d;
    if (is64) {
        const long long* p = (const long long*)ei;
        s = (int)p[i];
        d = (int)p[N_EDGES + i];
    } else {
        const int* p = (const int*)ei;
        s = p[i];
        d = p[N_EDGES + i];
    }
    int slot = atomicAdd(&g_deg[d], 1);
    if (slot < ELLPAD) g_ell[(size_t)d * ELLPAD + slot] = s;
}

// ---------------- mean aggregation (ELL): one warp per node ----------------
__global__ void k_agg(const float* __restrict__ H,
                      ushort_t* __restrict__ Ph, ushort_t* __restrict__ Pl) {
    int node = (blockIdx.x * blockDim.x + threadIdx.x) >> 5;
    int lane = threadIdx.x & 31;
    if (node >= N_NODES) return;
    const int* ell = g_ell + (size_t)node * ELLPAD;
    int d = g_deg[node];
    int dcap = min(d, ELLPAD);
    float4 acc = make_float4(0.f, 0.f, 0.f, 0.f);
    int e = 0;
    for (; e + 4 <= dcap; e += 4) {
        int s0 = ell[e], s1 = ell[e + 1], s2 = ell[e + 2], s3 = ell[e + 3];
        float4 v0 = ((const float4*)(H + (size_t)s0 * HIDF))[lane];
        float4 v1 = ((const float4*)(H + (size_t)s1 * HIDF))[lane];
        float4 v2 = ((const float4*)(H + (size_t)s2 * HIDF))[lane];
        float4 v3 = ((const float4*)(H + (size_t)s3 * HIDF))[lane];
        acc.x += (v0.x + v1.x) + (v2.x + v3.x);
        acc.y += (v0.y + v1.y) + (v2.y + v3.y);
        acc.z += (v0.z + v1.z) + (v2.z + v3.z);
        acc.w += (v0.w + v1.w) + (v2.w + v3.w);
    }
    for (; e < dcap; e++) {
        int s0 = ell[e];
        float4 v0 = ((const float4*)(H + (size_t)s0 * HIDF))[lane];
        acc.x += v0.x; acc.y += v0.y; acc.z += v0.z; acc.w += v0.w;
    }
    float inv = 1.0f / (float)max(d, 1);
    acc.x *= inv; acc.y *= inv; acc.z *= inv; acc.w *= inv;
    ushort_t h0, h1, h2, h3, l0, l1, l2, l3;
    bf_split(acc.x, h0, l0); bf_split(acc.y, h1, l1);
    bf_split(acc.z, h2, l2); bf_split(acc.w, h3, l3);
    ushort4 hv; hv.x = h0; hv.y = h1; hv.z = h2; hv.w = h3;
    ushort4 lv; lv.x = l0; lv.y = l1; lv.z = l2; lv.w = l3;
    size_t o = (size_t)node * HIDF + lane * 4;
    *(ushort4*)(Ph + o) = hv;
    *(ushort4*)(Pl + o) = lv;
}

// ---------------- cp.async double-buffered bf16-split HMMA GEMM ----------------
// Swizzled 64B-row tiles (no padding): physical 16B-chunk = c ^ ((row>>1)&3).
// smem: 2 stages x 4 tiles x 8KB = 64KB -> 3 CTAs/SM.
#define TILEB 8192
#define GSMEM (2 * 4 * TILEB)

__device__ __forceinline__ uint32_t swz(int r, int c) {
    return (uint32_t)((r << 6) + ((c ^ ((r >> 1) & 3)) << 4));
}

__device__ __forceinline__ void stage_issue(
    int kb, int s, int row0, int r, int colseg, bool okA, uint32_t sb,
    const ushort_t* Aph, const ushort_t* Apl,
    const ushort_t* Hph, const ushort_t* Hpl,
    const ushort_t* Wh, const ushort_t* Wl)
{
    const ushort_t* Sh = (kb < 4) ? Aph : Hph;
    const ushort_t* Sl = (kb < 4) ? Apl : Hpl;
    int kc = (kb & 3) * 32;
    int k0 = kb * 32;
    int c0 = colseg >> 3;              // 16B-chunk index: 0 or 2
    uint32_t base = sb + (uint32_t)s * 4 * TILEB;
    uint32_t d0 = swz(r, c0), d1 = swz(r, c0 + 1);
    const ushort_t* gah = Sh + (size_t)(row0 + r) * HIDF + kc + colseg;
    const ushort_t* gal = Sl + (size_t)(row0 + r) * HIDF + kc + colseg;
    cp16z(base + 0 * TILEB + d0, gah,     okA);
    cp16z(base + 0 * TILEB + d1, gah + 8, okA);
    cp16z(base + 1 * TILEB + d0, gal,     okA);
    cp16z(base + 1 * TILEB + d1, gal + 8, okA);
    const ushort_t* gbh = Wh + (size_t)r * 256 + k0 + colseg;
    const ushort_t* gbl = Wl + (size_t)r * 256 + k0 + colseg;
    cp16(base + 2 * TILEB + d0, gbh);
    cp16(base + 2 * TILEB + d1, gbh + 8);
    cp16(base + 3 * TILEB + d0, gbl);
    cp16(base + 3 * TILEB + d1, gbl + 8);
    CP_COMMIT();
}

__global__ void __launch_bounds__(256)
k_gemm_pipe(const ushort_t* __restrict__ Aph, const ushort_t* __restrict__ Apl,
            const ushort_t* __restrict__ Hph, const ushort_t* __restrict__ Hpl,
            const ushort_t* __restrict__ Wh,  const ushort_t* __restrict__ Wl,
            const float* __restrict__ bias, float* __restrict__ Hout,
            ushort_t* __restrict__ Hoh, ushort_t* __restrict__ Hol) {
    extern __shared__ ushort_t sdyn[];
    __shared__ float bsm[128];
    uint32_t sb = smem_u32(sdyn);
    int tid = threadIdx.x;
    int warp = tid >> 5, lane = tid & 31;
    int wm = warp & 1, wn = warp >> 1;        // 2 x 4 warp grid
    int gq = lane >> 2, tig = lane & 3;       // quad-pair layout
    int row0 = blockIdx.x * 128;
    if (tid < 128) bsm[tid] = bias[tid];

    int r = tid >> 1;
    int colseg = (tid & 1) * 16;
    bool okA = (row0 + r) < N_NODES;
    int arow = (lane & 7) + 8 * ((lane >> 3) & 1);   // A row within 16
    int achk = lane >> 4;                            // A chunk sub-index 0/1
    int brow = lane & 7;                             // B row (n)
    int bchk = (lane >> 3) & 1;                      // B chunk sub-index 0/1

    float acc[4][4][4];
#pragma unroll
    for (int mi = 0; mi < 4; mi++)
#pragma unroll
        for (int ni = 0; ni < 4; ni++)
#pragma unroll
            for (int q = 0; q < 4; q++) acc[mi][ni][q] = 0.f;

    stage_issue(0, 0, row0, r, colseg, okA, sb, Aph, Apl, Hph, Hpl, Wh, Wl);

    for (int kb = 0; kb < 8; kb++) {
        int s = kb & 1;
        if (kb < 7) {
            stage_issue(kb + 1, s ^ 1, row0, r, colseg, okA, sb, Aph, Apl, Hph, Hpl, Wh, Wl);
            CP_WAIT(1);
        } else {
            CP_WAIT(0);
        }
        __syncthreads();
        uint32_t ah_s = sb + (uint32_t)(s * 4 + 0) * TILEB;
        uint32_t al_s = sb + (uint32_t)(s * 4 + 1) * TILEB;
        uint32_t bh_s = sb + (uint32_t)(s * 4 + 2) * TILEB;
        uint32_t bl_s = sb + (uint32_t)(s * 4 + 3) * TILEB;
#pragma unroll
        for (int ks = 0; ks < 2; ks++) {
            int ca = ks * 2 + achk;
            int cb = ks * 2 + bchk;
            unsigned ahf[4][4], alf[4][4], bhf[4][2], blf[4][2];
#pragma unroll
            for (int mi = 0; mi < 4; mi++) {
                int m = wm * 64 + mi * 16 + arow;
                uint32_t off = swz(m, ca);
                ldsm_x4(ahf[mi], ah_s + off);
                ldsm_x4(alf[mi], al_s + off);
            }
#pragma unroll
            for (int ni = 0; ni < 4; ni++) {
                int n = wn * 32 + ni * 8 + brow;
                uint32_t off = swz(n, cb);
                ldsm_x2(bhf[ni], bh_s + off);
                ldsm_x2(blf[ni], bl_s + off);
            }
#pragma unroll
            for (int mi = 0; mi < 4; mi++)
#pragma unroll
                for (int ni = 0; ni < 4; ni++) {
                    mma_bf16(acc[mi][ni], ahf[mi], bhf[ni]);
                    mma_bf16(acc[mi][ni], ahf[mi], blf[ni]);
                    mma_bf16(acc[mi][ni], alf[mi], bhf[ni]);
                }
        }
        __syncthreads();
    }
    // ---- epilogue + optional plane writes ----
    bool wrp = (Hoh != nullptr);
#pragma unroll
    for (int mi = 0; mi < 4; mi++) {
#pragma unroll
        for (int ni = 0; ni < 4; ni++) {
            int colc = wn * 32 + ni * 8 + tig * 2;
            int ra = row0 + wm * 64 + mi * 16 + gq;
            int rb = ra + 8;
            if (ra < N_NODES) {
                float2 o;
                o.x = fmaxf(acc[mi][ni][0] + bsm[colc], 0.f);
                o.y = fmaxf(acc[mi][ni][1] + bsm[colc + 1], 0.f);
                *(float2*)(Hout + (size_t)ra * HIDF + colc) = o;
                if (wrp) {
                    ushort_t hx, lx, hy, ly;
                    bf_split(o.x, hx, lx); bf_split(o.y, hy, ly);
                    ushort2 hv; hv.x = hx; hv.y = hy;
                    ushort2 lv; lv.x = lx; lv.y = ly;
                    *(ushort2*)(Hoh + (size_t)ra * HIDF + colc) = hv;
                    *(ushort2*)(Hol + (size_t)ra * HIDF + colc) = lv;
                }
            }
            if (rb < N_NODES) {
                float2 o;
                o.x = fmaxf(acc[mi][ni][2] + bsm[colc], 0.f);
                o.y = fmaxf(acc[mi][ni][3] + bsm[colc + 1], 0.f);
                *(float2*)(Hout + (size_t)rb * HIDF + colc) = o;
                if (wrp) {
                    ushort_t hx, lx, hy, ly;
                    bf_split(o.x, hx, lx); bf_split(o.y, hy, ly);
                    ushort2 hv; hv.x = hx; hv.y = hy;
                    ushort2 lv; lv.x = lx; lv.y = ly;
                    *(ushort2*)(Hoh + (size_t)rb * HIDF + colc) = hv;
                    *(ushort2*)(Hol + (size_t)rb * HIDF + colc) = lv;
                }
            }
        }
    }
}

// ---------------- sorted segment-mean pooling (128 nodes/block) ----------------
__global__ void k_pool(const float* __restrict__ H) {
    int t = threadIdx.x;
    int base = blockIdx.x * 128;
    if (base >= N_NODES) return;
    int end = min(base + 128, N_NODES);
    int cur = g_batch[base];
    float acc = 0.f;
    int run = 0;
    for (int n = base; n < end; n++) {
        int g = g_batch[n];
        if (g != cur) {
            atomicAdd(&g_pool[cur * HIDF + t], acc);
            if (t == 0) atomicAdd(&g_cnt[cur], run);
            acc = 0.f; run = 0; cur = g;
        }
        acc += H[(size_t)n * HIDF + t];
        run++;
    }
    atomicAdd(&g_pool[cur * HIDF + t], acc);
    if (t == 0) atomicAdd(&g_cnt[cur], run);
}

// ---------------- head: one block per graph, one warp per output ----------------
__global__ void k_head(const float* __restrict__ embed, const float* __restrict__ Wlin,
                       const float* __restrict__ blin, float* __restrict__ out) {
    int g = blockIdx.x;
    int o = threadIdx.x >> 5;      // 8 warps, one per output
    int lane = threadIdx.x & 31;
    float c = (float)max(g_cnt[g], 1);
    float inv = 1.0f / c;
    const float* wr = Wlin + o * (HIDF + EMBF);
    float s = 0.f;
    for (int k = lane; k < HIDF; k += 32) s += g_pool[g * HIDF + k] * inv * wr[k];
    for (int k = lane; k < EMBF; k += 32) s += embed[g * EMBF + k] * wr[HIDF + k];
#pragma unroll
    for (int off = 16; off > 0; off >>= 1)
        s += __shfl_down_sync(0xFFFFFFFF, s, off);
    if (lane == 0) out[g * OUTF + o] = s + blin[o];
}

// ---------------- launch ----------------
extern "C" void kernel_launch(void* const* d_in, const int* in_sizes, int n_in,
                              void* d_out, int out_size) {
    const float* x     = (const float*)d_in[0];
    const void*  ei    = d_in[1];
    const void*  batch = d_in[2];
    const float* embed = (const float*)d_in[3];
    const float* W1l   = (const float*)d_in[4];
    const float* b1l   = (const float*)d_in[5];
    const float* W1r   = (const float*)d_in[6];
    const float* W2l   = (const float*)d_in[7];
    const float* b2l   = (const float*)d_in[8];
    const float* W2r   = (const float*)d_in[9];
    const float* Wlin  = (const float*)d_in[10];
    const float* blin  = (const float*)d_in[11];
    float* out = (float*)d_out;

    float *h1_p, *h2_p;
    ushort_t *xh_p, *xl_p, *h1h_p, *h1l_p, *agh_p, *agl_p;
    ushort_t *wh1_p, *wl1_p, *wh2_p, *wl2_p;
    cudaGetSymbolAddress((void**)&h1_p,  g_h1);
    cudaGetSymbolAddress((void**)&h2_p,  g_h2);
    cudaGetSymbolAddress((void**)&xh_p,  g_xh);
    cudaGetSymbolAddress((void**)&xl_p,  g_xl);
    cudaGetSymbolAddress((void**)&h1h_p, g_h1h);
    cudaGetSymbolAddress((void**)&h1l_p, g_h1l);
    cudaGetSymbolAddress((void**)&agh_p, g_agh);
    cudaGetSymbolAddress((void**)&agl_p, g_agl);
    cudaGetSymbolAddress((void**)&wh1_p, g_wh1);
    cudaGetSymbolAddress((void**)&wl1_p, g_wl1);
    cudaGetSymbolAddress((void**)&wh2_p, g_wh2);
    cudaGetSymbolAddress((void**)&wl2_p, g_wl2);

    cudaFuncSetAttribute(k_gemm_pipe, cudaFuncAttributeMaxDynamicSharedMemorySize, GSMEM);

    const int TB = 256;
    const int n4 = N_NODES * HIDF / 4;
    k_prep_init<<<(n4 + TB - 1) / TB, TB>>>(x, ei, batch, W1l, W1r, W2l, W2r);   // 1
    k_fill_ell<<<(N_EDGES + TB - 1) / TB, TB>>>(ei);                              // 2

    const int NB = (N_NODES + 127) / 128;
    // layer 1
    k_agg<<<(N_NODES + 7) / 8, 256>>>(x, agh_p, agl_p);                           // 3
    k_gemm_pipe<<<NB, 256, GSMEM>>>(agh_p, agl_p, xh_p, xl_p, wh1_p, wl1_p,
                                    b1l, h1_p, h1h_p, h1l_p);                     // 4 <- profiled
    // layer 2
    k_agg<<<(N_NODES + 7) / 8, 256>>>(h1_p, agh_p, agl_p);                        // 5
    k_gemm_pipe<<<NB, 256, GSMEM>>>(agh_p, agl_p, h1h_p, h1l_p, wh2_p, wl2_p,
                                    b2l, h2_p, (ushort_t*)nullptr, (ushort_t*)nullptr);  // 6
    // pooling + head
    k_pool<<<(N_NODES + 127) / 128, 128>>>(h2_p);                                  // 7
    k_head<<<N_GRAPHS, 256>>>(embed, Wlin, blin, out);                             // 8
}

// round 12
// speedup vs baseline: 1.6234x; 1.0014x over previous
#include <cuda_runtime.h>
#include <cstdint>

typedef unsigned short ushort_t;

#define N_NODES   100000
#define N_EDGES   800000
#define HIDF      128
#define EMBF      64
#define OUTF      8
#define N_GRAPHS  64
#define ELLPAD    64

// ---------------- scratch (device globals; no allocation) ----------------
__device__ int   g_batch[N_NODES];
__device__ int   g_deg[N_NODES];
__device__ int   g_ell[(size_t)N_NODES * ELLPAD];
__device__ float g_h1 [(size_t)N_NODES * HIDF];
__device__ float g_h2 [(size_t)N_NODES * HIDF];
// bf16 hi/lo planes
__device__ ushort_t g_xh [(size_t)N_NODES * HIDF];
__device__ ushort_t g_xl [(size_t)N_NODES * HIDF];
__device__ ushort_t g_h1h[(size_t)N_NODES * HIDF];
__device__ ushort_t g_h1l[(size_t)N_NODES * HIDF];
__device__ ushort_t g_agh[(size_t)N_NODES * HIDF];
__device__ ushort_t g_agl[(size_t)N_NODES * HIDF];
// weights pre-split to bf16 hi/lo, layout [128 out][256 k] row-major
__device__ ushort_t g_wh1[128 * 256];
__device__ ushort_t g_wl1[128 * 256];
__device__ ushort_t g_wh2[128 * 256];
__device__ ushort_t g_wl2[128 * 256];
__device__ float g_pool[N_GRAPHS * HIDF];
__device__ int   g_cnt[N_GRAPHS];

// ---------------- helpers ----------------
__device__ __forceinline__ uint32_t smem_u32(const void* p) {
    uint32_t a;
    asm("{ .reg .u64 t; cvta.to.shared.u64 t, %1; cvt.u32.u64 %0, t; }" : "=r"(a) : "l"(p));
    return a;
}
__device__ __forceinline__ void bf_split(float v, ushort_t& h, ushort_t& l) {
    asm("cvt.rn.bf16.f32 %0, %1;" : "=h"(h) : "f"(v));
    float hf = __uint_as_float(((unsigned)h) << 16);
    float r = v - hf;
    asm("cvt.rn.bf16.f32 %0, %1;" : "=h"(l) : "f"(r));
}
// int64-vs-int32 detection from 8 fixed odd 32-bit words of edge_index.
__device__ __forceinline__ int ei_is64(const unsigned* w) {
    unsigned o = w[1] | w[3] | w[5] | w[7] | w[9] | w[11] | w[13] | w[15];
    return o == 0u;
}
__device__ __forceinline__ void cp16(uint32_t dst, const void* src) {
    asm volatile("cp.async.cg.shared.global [%0], [%1], 16;" :: "r"(dst), "l"(src));
}
__device__ __forceinline__ void cp16z(uint32_t dst, const void* src, bool ok) {
    int sz = ok ? 16 : 0;
    asm volatile("cp.async.cg.shared.global [%0], [%1], 16, %2;"
                 :: "r"(dst), "l"(src), "r"(sz));
}
#define CP_COMMIT() asm volatile("cp.async.commit_group;" ::: "memory")
#define CP_WAIT(n)  asm volatile("cp.async.wait_group %0;" :: "n"(n) : "memory")

__device__ __forceinline__ void ldsm_x4(unsigned* r, uint32_t a) {
    asm volatile("ldmatrix.sync.aligned.m8n8.x4.shared.b16 {%0,%1,%2,%3}, [%4];"
                 : "=r"(r[0]), "=r"(r[1]), "=r"(r[2]), "=r"(r[3]) : "r"(a));
}
__device__ __forceinline__ void ldsm_x2(unsigned* r, uint32_t a) {
    asm volatile("ldmatrix.sync.aligned.m8n8.x2.shared.b16 {%0,%1}, [%2];"
                 : "=r"(r[0]), "=r"(r[1]) : "r"(a));
}
__device__ __forceinline__ void mma_bf16(float* c, const unsigned* a, const unsigned* b) {
    asm volatile(
        "mma.sync.aligned.m16n8k16.row.col.f32.bf16.bf16.f32 "
        "{%0,%1,%2,%3}, {%4,%5,%6,%7}, {%8,%9}, {%0,%1,%2,%3};"
        : "+f"(c[0]), "+f"(c[1]), "+f"(c[2]), "+f"(c[3])
        : "r"(a[0]), "r"(a[1]), "r"(a[2]), "r"(a[3]), "r"(b[0]), "r"(b[1]));
}

// ---------------- fused prep: x split + weight split + batch + zeroing ----------------
__global__ void k_prep_init(const float* __restrict__ x, const void* __restrict__ ei,
                            const void* __restrict__ batch,
                            const float* __restrict__ W1l, const float* __restrict__ W1r,
                            const float* __restrict__ W2l, const float* __restrict__ W2r) {
    int idx = blockIdx.x * blockDim.x + threadIdx.x;
    const int n4 = N_NODES * HIDF / 4;
    if (idx < n4) {  // split x -> bf16 hi/lo planes
        float4 v = ((const float4*)x)[idx];
        ushort_t h0, h1, h2, h3, l0, l1, l2, l3;
        bf_split(v.x, h0, l0); bf_split(v.y, h1, l1);
        bf_split(v.z, h2, l2); bf_split(v.w, h3, l3);
        ushort4 hv; hv.x = h0; hv.y = h1; hv.z = h2; hv.w = h3;
        ushort4 lv; lv.x = l0; lv.y = l1; lv.z = l2; lv.w = l3;
        ((ushort4*)g_xh)[idx] = hv;
        ((ushort4*)g_xl)[idx] = lv;
    }
    if (idx < 128 * 256) {  // weight concat + split
        int j = idx >> 8, k = idx & 255;
        float w1 = (k < 128) ? W1l[j * 128 + k] : W1r[j * 128 + (k - 128)];
        float w2 = (k < 128) ? W2l[j * 128 + k] : W2r[j * 128 + (k - 128)];
        ushort_t h, l;
        bf_split(w1, h, l); g_wh1[idx] = h; g_wl1[idx] = l;
        bf_split(w2, h, l); g_wh2[idx] = h; g_wl2[idx] = l;
    }
    if (idx < N_NODES) {  // batch convert + zero deg
        int is64 = ei_is64((const unsigned*)ei);
        if (is64) g_batch[idx] = (int)((const long long*)batch)[idx];
        else      g_batch[idx] = ((const int*)batch)[idx];
        g_deg[idx] = 0;
    }
    if (idx < N_GRAPHS * HIDF) g_pool[idx] = 0.f;
    if (idx < N_GRAPHS)        g_cnt[idx]  = 0;
}

// ---------------- ELL build: convert edges inline + atomic cursor ----------------
__global__ void k_fill_ell(const void* __restrict__ ei) {
    int i = blockIdx.x * blockDim.x + threadIdx.x;
    if (i >= N_EDGES) return;
    int is64 = ei_is64((const unsigned*)ei);
    int s, d;
    if (is64) {
        const long long* p = (const long long*)ei;
        s = (int)p[i];
        d = (int)p[N_EDGES + i];
    } else {
        const int* p = (const int*)ei;
        s = p[i];
        d = p[N_EDGES + i];
    }
    int slot = atomicAdd(&g_deg[d], 1);
    if (slot < ELLPAD) g_ell[(size_t)d * ELLPAD + slot] = s;
}

// ---------------- mean aggregation (ELL): one warp per node ----------------
__global__ void k_agg(const float* __restrict__ H,
                      ushort_t* __restrict__ Ph, ushort_t* __restrict__ Pl) {
    int node = (blockIdx.x * blockDim.x + threadIdx.x) >> 5;
    int lane = threadIdx.x & 31;
    if (node >= N_NODES) return;
    const int* ell = g_ell + (size_t)node * ELLPAD;
    int d = g_deg[node];
    int dcap = min(d, ELLPAD);
    float4 acc = make_float4(0.f, 0.f, 0.f, 0.f);
    int e = 0;
    for (; e + 4 <= dcap; e += 4) {
        int s0 = ell[e], s1 = ell[e + 1], s2 = ell[e + 2], s3 = ell[e + 3];
        float4 v0 = ((const float4*)(H + (size_t)s0 * HIDF))[lane];
        float4 v1 = ((const float4*)(H + (size_t)s1 * HIDF))[lane];
        float4 v2 = ((const float4*)(H + (size_t)s2 * HIDF))[lane];
        float4 v3 = ((const float4*)(H + (size_t)s3 * HIDF))[lane];
        acc.x += (v0.x + v1.x) + (v2.x + v3.x);
        acc.y += (v0.y + v1.y) + (v2.y + v3.y);
        acc.z += (v0.z + v1.z) + (v2.z + v3.z);
        acc.w += (v0.w + v1.w) + (v2.w + v3.w);
    }
    for (; e < dcap; e++) {
        int s0 = ell[e];
        float4 v0 = ((const float4*)(H + (size_t)s0 * HIDF))[lane];
        acc.x += v0.x; acc.y += v0.y; acc.z += v0.z; acc.w += v0.w;
    }
    float inv = 1.0f / (float)max(d, 1);
    acc.x *= inv; acc.y *= inv; acc.z *= inv; acc.w *= inv;
    ushort_t h0, h1, h2, h3, l0, l1, l2, l3;
    bf_split(acc.x, h0, l0); bf_split(acc.y, h1, l1);
    bf_split(acc.z, h2, l2); bf_split(acc.w, h3, l3);
    ushort4 hv; hv.x = h0; hv.y = h1; hv.z = h2; hv.w = h3;
    ushort4 lv; lv.x = l0; lv.y = l1; lv.z = l2; lv.w = l3;
    size_t o = (size_t)node * HIDF + lane * 4;
    *(ushort4*)(Ph + o) = hv;
    *(ushort4*)(Pl + o) = lv;
}

// ---------------- cp.async 3-stage bf16-split HMMA GEMM ----------------
// Swizzled 64B-row tiles: physical 16B-chunk = c ^ ((row>>1)&3).
// smem: 3 stages x 4 tiles x 8KB = 96KB; 2 CTAs/SM (reg-bound anyway);
// prefetch depth 2 kb -> ~2 kb of global latency hidden.
#define TILEB 8192
#define NSTG  3
#define GSMEM (NSTG * 4 * TILEB)

__device__ __forceinline__ uint32_t swz(int r, int c) {
    return (uint32_t)((r << 6) + ((c ^ ((r >> 1) & 3)) << 4));
}

__device__ __forceinline__ void stage_issue(
    int kb, int s, int row0, int r, int colseg, bool okA, uint32_t sb,
    const ushort_t* Aph, const ushort_t* Apl,
    const ushort_t* Hph, const ushort_t* Hpl,
    const ushort_t* Wh, const ushort_t* Wl)
{
    const ushort_t* Sh = (kb < 4) ? Aph : Hph;
    const ushort_t* Sl = (kb < 4) ? Apl : Hpl;
    int kc = (kb & 3) * 32;
    int k0 = kb * 32;
    int c0 = colseg >> 3;              // 16B-chunk index: 0 or 2
    uint32_t base = sb + (uint32_t)s * 4 * TILEB;
    uint32_t d0 = swz(r, c0), d1 = swz(r, c0 + 1);
    const ushort_t* gah = Sh + (size_t)(row0 + r) * HIDF + kc + colseg;
    const ushort_t* gal = Sl + (size_t)(row0 + r) * HIDF + kc + colseg;
    cp16z(base + 0 * TILEB + d0, gah,     okA);
    cp16z(base + 0 * TILEB + d1, gah + 8, okA);
    cp16z(base + 1 * TILEB + d0, gal,     okA);
    cp16z(base + 1 * TILEB + d1, gal + 8, okA);
    const ushort_t* gbh = Wh + (size_t)r * 256 + k0 + colseg;
    const ushort_t* gbl = Wl + (size_t)r * 256 + k0 + colseg;
    cp16(base + 2 * TILEB + d0, gbh);
    cp16(base + 2 * TILEB + d1, gbh + 8);
    cp16(base + 3 * TILEB + d0, gbl);
    cp16(base + 3 * TILEB + d1, gbl + 8);
    CP_COMMIT();
}

__global__ void __launch_bounds__(256)
k_gemm_pipe(const ushort_t* __restrict__ Aph, const ushort_t* __restrict__ Apl,
            const ushort_t* __restrict__ Hph, const ushort_t* __restrict__ Hpl,
            const ushort_t* __restrict__ Wh,  const ushort_t* __restrict__ Wl,
            const float* __restrict__ bias, float* __restrict__ Hout,
            ushort_t* __restrict__ Hoh, ushort_t* __restrict__ Hol) {
    extern __shared__ ushort_t sdyn[];
    __shared__ float bsm[128];
    uint32_t sb = smem_u32(sdyn);
    int tid = threadIdx.x;
    int warp = tid >> 5, lane = tid & 31;
    int wm = warp & 1, wn = warp >> 1;        // 2 x 4 warp grid
    int gq = lane >> 2, tig = lane & 3;       // quad-pair layout
    int row0 = blockIdx.x * 128;
    if (tid < 128) bsm[tid] = bias[tid];

    int r = tid >> 1;
    int colseg = (tid & 1) * 16;
    bool okA = (row0 + r) < N_NODES;
    int arow = (lane & 7) + 8 * ((lane >> 3) & 1);   // A row within 16
    int achk = lane >> 4;                            // A chunk sub-index 0/1
    int brow = lane & 7;                             // B row (n)
    int bchk = (lane >> 3) & 1;                      // B chunk sub-index 0/1

    float acc[4][4][4];
#pragma unroll
    for (int mi = 0; mi < 4; mi++)
#pragma unroll
        for (int ni = 0; ni < 4; ni++)
#pragma unroll
            for (int q = 0; q < 4; q++) acc[mi][ni][q] = 0.f;

    stage_issue(0, 0, row0, r, colseg, okA, sb, Aph, Apl, Hph, Hpl, Wh, Wl);
    stage_issue(1, 1, row0, r, colseg, okA, sb, Aph, Apl, Hph, Hpl, Wh, Wl);

    for (int kb = 0; kb < 8; kb++) {
        int s = kb % NSTG;
        if (kb + 2 < 8) {
            stage_issue(kb + 2, (kb + 2) % NSTG, row0, r, colseg, okA, sb,
                        Aph, Apl, Hph, Hpl, Wh, Wl);
            CP_WAIT(2);
        } else if (kb + 1 < 8) {
            CP_WAIT(1);
        } else {
            CP_WAIT(0);
        }
        __syncthreads();
        uint32_t ah_s = sb + (uint32_t)(s * 4 + 0) * TILEB;
        uint32_t al_s = sb + (uint32_t)(s * 4 + 1) * TILEB;
        uint32_t bh_s = sb + (uint32_t)(s * 4 + 2) * TILEB;
        uint32_t bl_s = sb + (uint32_t)(s * 4 + 3) * TILEB;
#pragma unroll
        for (int ks = 0; ks < 2; ks++) {
            int ca = ks * 2 + achk;
            int cb = ks * 2 + bchk;
            unsigned ahf[4][4], alf[4][4], bhf[4][2], blf[4][2];
#pragma unroll
            for (int mi = 0; mi < 4; mi++) {
                int m = wm * 64 + mi * 16 + arow;
                uint32_t off = swz(m, ca);
                ldsm_x4(ahf[mi], ah_s + off);
                ldsm_x4(alf[mi], al_s + off);
            }
#pragma unroll
            for (int ni = 0; ni < 4; ni++) {
                int n = wn * 32 + ni * 8 + brow;
                uint32_t off = swz(n, cb);
                ldsm_x2(bhf[ni], bh_s + off);
                ldsm_x2(blf[ni], bl_s + off);
            }
#pragma unroll
            for (int mi = 0; mi < 4; mi++)
#pragma unroll
                for (int ni = 0; ni < 4; ni++) {
                    mma_bf16(acc[mi][ni], ahf[mi], bhf[ni]);
                    mma_bf16(acc[mi][ni], ahf[mi], blf[ni]);
                    mma_bf16(acc[mi][ni], alf[mi], bhf[ni]);
                }
        }
        __syncthreads();
    }
    // ---- epilogue + optional plane writes ----
    bool wrp = (Hoh != nullptr);
#pragma unroll
    for (int mi = 0; mi < 4; mi++) {
#pragma unroll
        for (int ni = 0; ni < 4; ni++) {
            int colc = wn * 32 + ni * 8 + tig * 2;
            int ra = row0 + wm * 64 + mi * 16 + gq;
            int rb = ra + 8;
            if (ra < N_NODES) {
                float2 o;
                o.x = fmaxf(acc[mi][ni][0] + bsm[colc], 0.f);
                o.y = fmaxf(acc[mi][ni][1] + bsm[colc + 1], 0.f);
                *(float2*)(Hout + (size_t)ra * HIDF + colc) = o;
                if (wrp) {
                    ushort_t hx, lx, hy, ly;
                    bf_split(o.x, hx, lx); bf_split(o.y, hy, ly);
                    ushort2 hv; hv.x = hx; hv.y = hy;
                    ushort2 lv; lv.x = lx; lv.y = ly;
                    *(ushort2*)(Hoh + (size_t)ra * HIDF + colc) = hv;
                    *(ushort2*)(Hol + (size_t)ra * HIDF + colc) = lv;
                }
            }
            if (rb < N_NODES) {
                float2 o;
                o.x = fmaxf(acc[mi][ni][2] + bsm[colc], 0.f);
                o.y = fmaxf(acc[mi][ni][3] + bsm[colc + 1], 0.f);
                *(float2*)(Hout + (size_t)rb * HIDF + colc) = o;
                if (wrp) {
                    ushort_t hx, lx, hy, ly;
                    bf_split(o.x, hx, lx); bf_split(o.y, hy, ly);
                    ushort2 hv; hv.x = hx; hv.y = hy;
                    ushort2 lv; lv.x = lx; lv.y = ly;
                    *(ushort2*)(Hoh + (size_t)rb * HIDF + colc) = hv;
                    *(ushort2*)(Hol + (size_t)rb * HIDF + colc) = lv;
                }
            }
        }
    }
}

// ---------------- sorted segment-mean pooling (128 nodes/block) ----------------
__global__ void k_pool(const float* __restrict__ H) {
    int t = threadIdx.x;
    int base = blockIdx.x * 128;
    if (base >= N_NODES) return;
    int end = min(base + 128, N_NODES);
    int cur = g_batch[base];
    float acc = 0.f;
    int run = 0;
    for (int n = base; n < end; n++) {
        int g = g_batch[n];
        if (g != cur) {
            atomicAdd(&g_pool[cur * HIDF + t], acc);
            if (t == 0) atomicAdd(&g_cnt[cur], run);
            acc = 0.f; run = 0; cur = g;
        }
        acc += H[(size_t)n * HIDF + t];
        run++;
    }
    atomicAdd(&g_pool[cur * HIDF + t], acc);
    if (t == 0) atomicAdd(&g_cnt[cur], run);
}

// ---------------- head: one block per graph, one warp per output ----------------
__global__ void k_head(const float* __restrict__ embed, const float* __restrict__ Wlin,
                       const float* __restrict__ blin, float* __restrict__ out) {
    int g = blockIdx.x;
    int o = threadIdx.x >> 5;      // 8 warps, one per output
    int lane = threadIdx.x & 31;
    float c = (float)max(g_cnt[g], 1);
    float inv = 1.0f / c;
    const float* wr = Wlin + o * (HIDF + EMBF);
    float s = 0.f;
    for (int k = lane; k < HIDF; k += 32) s += g_pool[g * HIDF + k] * inv * wr[k];
    for (int k = lane; k < EMBF; k += 32) s += embed[g * EMBF + k] * wr[HIDF + k];
#pragma unroll
    for (int off = 16; off > 0; off >>= 1)
        s += __shfl_down_sync(0xFFFFFFFF, s, off);
    if (lane == 0) out[g * OUTF + o] = s + blin[o];
}

// ---------------- launch ----------------
extern "C" void kernel_launch(void* const* d_in, const int* in_sizes, int n_in,
                              void* d_out, int out_size) {
    const float* x     = (const float*)d_in[0];
    const void*  ei    = d_in[1];
    const void*  batch = d_in[2];
    const float* embed = (const float*)d_in[3];
    const float* W1l   = (const float*)d_in[4];
    const float* b1l   = (const float*)d_in[5];
    const float* W1r   = (const float*)d_in[6];
    const float* W2l   = (const float*)d_in[7];
    const float* b2l   = (const float*)d_in[8];
    const float* W2r   = (const float*)d_in[9];
    const float* Wlin  = (const float*)d_in[10];
    const float* blin  = (const float*)d_in[11];
    float* out = (float*)d_out;

    float *h1_p, *h2_p;
    ushort_t *xh_p, *xl_p, *h1h_p, *h1l_p, *agh_p, *agl_p;
    ushort_t *wh1_p, *wl1_p, *wh2_p, *wl2_p;
    cudaGetSymbolAddress((void**)&h1_p,  g_h1);
    cudaGetSymbolAddress((void**)&h2_p,  g_h2);
    cudaGetSymbolAddress((void**)&xh_p,  g_xh);
    cudaGetSymbolAddress((void**)&xl_p,  g_xl);
    cudaGetSymbolAddress((void**)&h1h_p, g_h1h);
    cudaGetSymbolAddress((void**)&h1l_p, g_h1l);
    cudaGetSymbolAddress((void**)&agh_p, g_agh);
    cudaGetSymbolAddress((void**)&agl_p, g_agl);
    cudaGetSymbolAddress((void**)&wh1_p, g_wh1);
    cudaGetSymbolAddress((void**)&wl1_p, g_wl1);
    cudaGetSymbolAddress((void**)&wh2_p, g_wh2);
    cudaGetSymbolAddress((void**)&wl2_p, g_wl2);

    cudaFuncSetAttribute(k_gemm_pipe, cudaFuncAttributeMaxDynamicSharedMemorySize, GSMEM);

    const int TB = 256;
    const int n4 = N_NODES * HIDF / 4;
    k_prep_init<<<(n4 + TB - 1) / TB, TB>>>(x, ei, batch, W1l, W1r, W2l, W2r);   // 1
    k_fill_ell<<<(N_EDGES + TB - 1) / TB, TB>>>(ei);                              // 2

    const int NB = (N_NODES + 127) / 128;
    // layer 1
    k_agg<<<(N_NODES + 7) / 8, 256>>>(x, agh_p, agl_p);                           // 3
    k_gemm_pipe<<<NB, 256, GSMEM>>>(agh_p, agl_p, xh_p, xl_p, wh1_p, wl1_p,
                                    b1l, h1_p, h1h_p, h1l_p);                     // 4 <- profiled
    // layer 2
    k_agg<<<(N_NODES + 7) / 8, 256>>>(h1_p, agh_p, agl_p);                        // 5
    k_gemm_pipe<<<NB, 256, GSMEM>>>(agh_p, agl_p, h1h_p, h1l_p, wh2_p, wl2_p,
                                    b2l, h2_p, (ushort_t*)nullptr, (ushort_t*)nullptr);  // 6
    // pooling + head
    k_pool<<<(N_NODES + 127) / 128, 128>>>(h2_p);                                  // 7
    k_head<<<N_GRAPHS, 256>>>(embed, Wlin, blin, out);                             // 8
}